// round 1
// baseline (speedup 1.0000x reference)
#include <cuda_runtime.h>
#include <cstdint>

// ---------------------------------------------------------------------------
// MemristiveLinear: reference algebra collapses exactly to  y = x @ w + b.
//   g_pos - g_neg = k_cond * weights  (G_OFF cancels), and the K_V / k_cond
//   scale factors divide out. So this is a 512x512x512 fp32 GEMM + bias.
//
// Implementation: split-K fp32 GEMM using packed fma.rn.f32x2 (FFMA2),
//   128 CTAs (32 tiles of 128x64 x 4 K-slices), 128 threads/CTA,
//   8x8 micro-tile per thread (4 f32x2 pairs in N), double-buffered smem,
//   register-staged global prefetch. A second kernel reduces the 4 K-slice
//   partials and adds bias.
// ---------------------------------------------------------------------------

#define M_DIM 512
#define N_DIM 512
#define K_DIM 512

#define BM 128
#define BN 64
#define BK 16
#define TM 8
#define TN 8
#define SPLITK 4
#define KSLICE (K_DIM / SPLITK)        // 128
#define KITERS (KSLICE / BK)           // 8
#define NTHREADS ((BM / TM) * (BN / TN))  // 128

// Split-K partial sums scratch (allocation-free rule: __device__ global).
__device__ float g_part[SPLITK * M_DIM * N_DIM];

__device__ __forceinline__ unsigned long long pack2(float lo, float hi) {
    unsigned long long r;
    asm("mov.b64 %0, {%1, %2};" : "=l"(r) : "f"(lo), "f"(hi));
    return r;
}

__device__ __forceinline__ void ffma2(unsigned long long& d,
                                      unsigned long long a,
                                      unsigned long long b) {
    asm volatile("fma.rn.f32x2 %0, %1, %2, %0;" : "+l"(d) : "l"(a), "l"(b));
}

__global__ __launch_bounds__(NTHREADS, 1)
void gemm_splitk_kernel(const float* __restrict__ X,
                        const float* __restrict__ W,
                        float* __restrict__ P) {
    __shared__ float xs[2][BK][BM];   // x tile, transposed (k-major rows, m contiguous)
    __shared__ float ws[2][BK][BN];   // w tile, natural

    const int tid = threadIdx.x;
    const int tn = tid & 7;           // 8 thread-groups in N
    const int tm = tid >> 3;          // 16 thread-groups in M
    const int n0 = blockIdx.x * BN;
    const int m0 = blockIdx.y * BM;
    const int kbase = blockIdx.z * KSLICE;

    // Global prefetch registers
    float4 xr[4];
    float4 wr[2];

    const float* xrow = X + (m0 + tid) * K_DIM + kbase;  // one M-row per thread

#define GLOAD(it)                                                            \
    do {                                                                     \
        const int kk_ = (it) * BK;                                           \
        _Pragma("unroll")                                                    \
        for (int j = 0; j < 4; j++)                                          \
            xr[j] = *(const float4*)(xrow + kk_ + 4 * j);                    \
        _Pragma("unroll")                                                    \
        for (int j = 0; j < 2; j++) {                                        \
            const int f_ = tid + NTHREADS * j;                               \
            const int kl_ = f_ >> 4, c4_ = f_ & 15;                          \
            wr[j] = *(const float4*)(W + (kbase + kk_ + kl_) * N_DIM + n0 +  \
                                     4 * c4_);                               \
        }                                                                    \
    } while (0)

#define STS(buf_)                                                            \
    do {                                                                     \
        _Pragma("unroll")                                                    \
        for (int j = 0; j < 4; j++) {                                        \
            xs[buf_][4 * j + 0][tid] = xr[j].x;                              \
            xs[buf_][4 * j + 1][tid] = xr[j].y;                              \
            xs[buf_][4 * j + 2][tid] = xr[j].z;                              \
            xs[buf_][4 * j + 3][tid] = xr[j].w;                              \
        }                                                                    \
        _Pragma("unroll")                                                    \
        for (int j = 0; j < 2; j++) {                                        \
            const int f_ = tid + NTHREADS * j;                               \
            const int kl_ = f_ >> 4, c4_ = f_ & 15;                          \
            *(float4*)&ws[buf_][kl_][4 * c4_] = wr[j];                       \
        }                                                                    \
    } while (0)

    unsigned long long acc[TM][TN / 2];
#pragma unroll
    for (int m = 0; m < TM; m++)
#pragma unroll
        for (int p = 0; p < TN / 2; p++)
            acc[m][p] = 0ull;  // bit pattern of {0.f, 0.f}

    GLOAD(0);
    STS(0);
    __syncthreads();

#pragma unroll
    for (int it = 0; it < KITERS; ++it) {
        const int buf = it & 1;
        if (it + 1 < KITERS) GLOAD(it + 1);

#pragma unroll
        for (int k = 0; k < BK; k++) {
            const float4 a0 = *(const float4*)&xs[buf][k][tm * TM];
            const float4 a1 = *(const float4*)&xs[buf][k][tm * TM + 4];
            const ulonglong2 b0 = *(const ulonglong2*)&ws[buf][k][tn * TN];
            const ulonglong2 b1 = *(const ulonglong2*)&ws[buf][k][tn * TN + 4];

            unsigned long long av[TM];
            av[0] = pack2(a0.x, a0.x);
            av[1] = pack2(a0.y, a0.y);
            av[2] = pack2(a0.z, a0.z);
            av[3] = pack2(a0.w, a0.w);
            av[4] = pack2(a1.x, a1.x);
            av[5] = pack2(a1.y, a1.y);
            av[6] = pack2(a1.z, a1.z);
            av[7] = pack2(a1.w, a1.w);

            unsigned long long bv[4];
            bv[0] = b0.x; bv[1] = b0.y; bv[2] = b1.x; bv[3] = b1.y;

#pragma unroll
            for (int m = 0; m < TM; m++)
#pragma unroll
                for (int p = 0; p < TN / 2; p++)
                    ffma2(acc[m][p], av[m], bv[p]);
        }

        if (it + 1 < KITERS) STS(buf ^ 1);
        __syncthreads();
    }

    // Epilogue: write partial tile
    float* out = P + (size_t)blockIdx.z * (M_DIM * N_DIM) +
                 (m0 + tm * TM) * N_DIM + n0 + tn * TN;
#pragma unroll
    for (int m = 0; m < TM; m++) {
        ulonglong2 v0, v1;
        v0.x = acc[m][0]; v0.y = acc[m][1];
        v1.x = acc[m][2]; v1.y = acc[m][3];
        *(ulonglong2*)(out + (size_t)m * N_DIM) = v0;
        *(ulonglong2*)(out + (size_t)m * N_DIM + 4) = v1;
    }
#undef GLOAD
#undef STS
}

__global__ __launch_bounds__(256)
void reduce_bias_kernel(const float* __restrict__ P,
                        const float* __restrict__ B,
                        float* __restrict__ Y) {
    const int idx = blockIdx.x * blockDim.x + threadIdx.x;  // float4 index
    const float4* p = (const float4*)P;
    const int stride4 = (M_DIM * N_DIM) / 4;  // 65536
    float4 a = p[idx];
    float4 b = p[idx + stride4];
    float4 c = p[idx + 2 * stride4];
    float4 d = p[idx + 3 * stride4];
    float4 bb = ((const float4*)B)[idx & (N_DIM / 4 - 1)];
    float4 r;
    r.x = a.x + b.x + c.x + d.x + bb.x;
    r.y = a.y + b.y + c.y + d.y + bb.y;
    r.z = a.z + b.z + c.z + d.z + bb.z;
    r.w = a.w + b.w + c.w + d.w + bb.w;
    ((float4*)Y)[idx] = r;
}

extern "C" void kernel_launch(void* const* d_in, const int* in_sizes, int n_in,
                              void* d_out, int out_size) {
    const float* x = (const float*)d_in[0];  // [512, 512]
    const float* w = (const float*)d_in[1];  // [512, 512]
    const float* b = (const float*)d_in[2];  // [512]
    float* y = (float*)d_out;                // [512, 512]

    float* part;
    cudaGetSymbolAddress((void**)&part, g_part);

    dim3 grid1(N_DIM / BN, M_DIM / BM, SPLITK);  // (8, 4, 4) = 128 CTAs
    gemm_splitk_kernel<<<grid1, NTHREADS>>>(x, w, part);

    const int n4 = (M_DIM * N_DIM) / 4;          // 65536
    reduce_bias_kernel<<<n4 / 256, 256>>>(part, b, y);
}